// round 7
// baseline (speedup 1.0000x reference)
#include <cuda_runtime.h>
#include <math.h>
#include <float.h>

#define MAXB 16
#define MAXA 33600
#define MAXT 50
#define NCLS 80
#define KC 10
#define TILE 1024
#define NCHK 33                  // ceil(MAXA / TILE)
#define BUFCAP 64
#define BUFTOT 80
#define PCAP 80                  // per (b,t,chunk) dump capacity (<= 74 used)
#define INV_LN2 1.4426950408889634f
#define PEN2 (100000.0f * 1.4426950408889634f)

// Scratch (static __device__ globals)
__device__ int    d_cnt [MAXB];
__device__ int    d_mcnt[MAXB];
__device__ int    d_mlist[MAXB][MAXT * KC + 32];
__device__ float4 d_gbox [MAXB][MAXA];
__device__ float4 d_gmeta[MAXB][MAXA];           // xc, yc, rad, aidx-as-float-bits
__device__ float  d_gct  [MAXB * MAXT * MAXA];   // [b][t][pos] coalesced
__device__ int    d_pos  [MAXB * MAXA];
__device__ int    d_count[MAXB * MAXA];
__device__ int    d_mint [MAXB * MAXA];
// k2a -> k2b partial dumps
__device__ float  d_pcv[MAXB * MAXT * NCHK][PCAP];
__device__ int    d_pci[MAXB * MAXT * NCHK][PCAP];
__device__ float  d_piv[MAXB * MAXT * NCHK][PCAP];
__device__ int    d_pcn[MAXB * MAXT * NCHK];
__device__ int    d_pin[MAXB * MAXT * NCHK];

__global__ void k0a_zero() {
    if (threadIdx.x < MAXB) d_cnt[threadIdx.x] = 0;
}
__global__ void k0b_zero() {
    if (threadIdx.x < MAXB) d_mcnt[threadIdx.x] = 0;
}

// ---------- warp-parallel selection helpers ----------
__device__ __forceinline__ void sel_cost(float* bufv, int* bufi, int total,
                                         float* topv, int* topi, int lane)
{
    int rounds = min(KC, total);
    for (int r = 0; r < rounds; r++) {
        float v = FLT_MAX; int id = 0x7fffffff; int sl = 0;
        for (int s = lane; s < total; s += 32) {
            float vv = bufv[s]; int ii = bufi[s];
            if (vv < v || (vv == v && ii < id)) { v = vv; id = ii; sl = s; }
        }
        #pragma unroll
        for (int off = 16; off; off >>= 1) {
            float ov = __shfl_xor_sync(0xffffffffu, v, off);
            int   oi = __shfl_xor_sync(0xffffffffu, id, off);
            int   os = __shfl_xor_sync(0xffffffffu, sl, off);
            if (ov < v || (ov == v && oi < id)) { v = ov; id = oi; sl = os; }
        }
        if (lane == 0) { topv[r] = v; topi[r] = id; bufv[sl] = FLT_MAX; bufi[sl] = 0x7fffffff; }
        __syncwarp();
    }
    if (lane >= rounds && lane < KC) { topv[lane] = FLT_MAX; topi[lane] = 0x7fffffff; }
    __syncwarp();
}

__device__ __forceinline__ void sel_iou(float* bufv, int total, float* topv, int lane)
{
    int rounds = min(KC, total);
    for (int r = 0; r < rounds; r++) {
        float v = -1.f; int sl = 0;
        for (int s = lane; s < total; s += 32) {
            float vv = bufv[s];
            if (vv > v) { v = vv; sl = s; }
        }
        #pragma unroll
        for (int off = 16; off; off >>= 1) {
            float ov = __shfl_xor_sync(0xffffffffu, v, off);
            int   os = __shfl_xor_sync(0xffffffffu, sl, off);
            if (ov > v) { v = ov; sl = os; }
        }
        if (lane == 0) { topv[r] = v; bufv[sl] = -1.f; }
        __syncwarp();
    }
    if (lane >= rounds && lane < KC) topv[lane] = -1.f;
    __syncwarp();
}

// K1: per-anchor. S2 = softplus-sum/ln2, iba flags, compaction (unchanged).
__global__ __launch_bounds__(128) void k1_anchor(
    const float* __restrict__ pred, const float* __restrict__ target,
    const float* __restrict__ grid, const float* __restrict__ stridem,
    int A, int T)
{
    __shared__ float sp[128 * 85];
    __shared__ float st[MAXT * 8];
    __shared__ int   scls[MAXT];

    int b    = blockIdx.y;
    int base = blockIdx.x * 128;
    int nrows = min(128, A - base);

    const float* predb = pred + ((size_t)b * A + base) * 84;
    for (int i = threadIdx.x; i < nrows * 84; i += 128) {
        int r = i / 84;
        int c = i - r * 84;
        sp[r * 85 + c] = predb[i];
    }
    for (int i = threadIdx.x; i < T; i += 128) {
        const float* tg = target + ((size_t)b * T + i) * 5;
        float cl = tg[0], x0 = tg[1], y0 = tg[2], x1 = tg[3], y1 = tg[4];
        st[i * 8 + 0] = x0; st[i * 8 + 1] = y0;
        st[i * 8 + 2] = x1; st[i * 8 + 3] = y1;
        st[i * 8 + 4] = 0.5f * (x0 + x1);
        st[i * 8 + 5] = 0.5f * (y0 + y1);
        scls[i] = (int)cl;
    }
    __syncthreads();

    int tid  = threadIdx.x;
    int lane = tid & 31;
    bool alive = (tid < nrows);
    int a = base + tid;

    bool iba = false;
    float S2 = 0.f, px0 = 0, py0 = 0, px1 = 0, py1 = 0, xc = 0, yc = 0, rad = 0;
    const float* row = sp + tid * 85;

    if (alive) {
        float strv = stridem[a];
        xc  = (grid[2 * a]     + 0.5f) * strv;
        yc  = (grid[2 * a + 1] + 0.5f) * strv;
        rad = 2.5f * strv;
        px0 = row[0]; py0 = row[1]; px1 = row[2]; py1 = row[3];

        float P = 1.f;
        int   E = 0;
        #pragma unroll 4
        for (int c = 0; c < NCLS; c++) {
            float e = __expf(row[4 + c]);
            P *= (1.f + e);
            if ((c & 3) == 3) {
                int bits = __float_as_int(P);
                E += ((bits >> 23) & 255) - 127;
                P = __int_as_float((bits & 0x007FFFFF) | 0x3F800000);
            }
        }
        S2 = (float)E + __log2f(P);

        bool anyB = false, anyC = false;
        for (int t = 0; t < T; t++) {
            float tx0 = st[t * 8 + 0], ty0 = st[t * 8 + 1];
            float tx1 = st[t * 8 + 2], ty1 = st[t * 8 + 3];
            float cxt = st[t * 8 + 4], cyt = st[t * 8 + 5];
            bool inB = fminf(fminf(xc - tx0, yc - ty0), fminf(tx1 - xc, ty1 - yc)) > 0.f;
            bool inC = fmaxf(fabsf(xc - cxt), fabsf(yc - cyt)) < rad;
            anyB |= inB; anyC |= inC;
        }
        iba = anyB || anyC;
    }

    unsigned m = __ballot_sync(0xffffffffu, iba);
    if (m) {
        int leader = __ffs(m) - 1;
        int wbase = 0;
        if (lane == leader) wbase = atomicAdd(&d_cnt[b], __popc(m));
        wbase = __shfl_sync(0xffffffffu, wbase, leader);
        if (iba) {
            int pos = wbase + __popc(m & ((1u << lane) - 1u));
            int gi = b * A + a;
            d_pos  [gi] = pos;
            d_count[gi] = 0;
            d_mint [gi] = 0x7fffffff;
            d_gbox [b][pos] = make_float4(px0, py0, px1, py1);
            d_gmeta[b][pos] = make_float4(xc, yc, rad, __int_as_float(a));
            float* gct = d_gct + (size_t)b * MAXT * MAXA + pos;
            for (int t = 0; t < T; t++)
                gct[(size_t)t * MAXA] = S2 - row[4 + scls[t]] * INV_LN2;
        }
    }
}

// K2a: block per (image, 1024-cand tile). Tile staged in smem once;
// each warp sequentially handles targets t = w, w+8, ... with the
// threshold-filter; dumps filtered entries (no selection here).
__global__ __launch_bounds__(256) void k2a_scan(
    const float* __restrict__ target, int A, int T)
{
    __shared__ float4 sbox [TILE];
    __shared__ float4 smeta[TILE];
    __shared__ float sbcv[8][BUFTOT]; __shared__ int sbci[8][BUFTOT];
    __shared__ float sbiv[8][BUFTOT];
    __shared__ float stcv[8][KC];     __shared__ int stci[8][KC];
    __shared__ float stiv[8][KC];

    int b     = blockIdx.y;
    int chunk = blockIdx.x;
    int N     = d_cnt[b];
    int tilebase = chunk * TILE;
    if (tilebase >= N) return;
    int nvalid = min(TILE, N - tilebase);

    int tid = threadIdx.x, w = tid >> 5, lane = tid & 31;

    for (int i = tid; i < TILE; i += 256) {
        int g = min(tilebase + i, N - 1);
        sbox [i] = d_gbox [b][g];
        smeta[i] = d_gmeta[b][g];
    }
    __syncthreads();

    int iters = (nvalid + 31) >> 5;

    for (int t = w; t < T; t += 8) {
        const float* tg = target + ((size_t)b * T + t) * 5;
        float tx0 = tg[1], ty0 = tg[2], tx1 = tg[3], ty1 = tg[4];
        float cxt = 0.5f * (tx0 + tx1), cyt = 0.5f * (ty0 + ty1);
        float areaT = (tx1 - tx0) * (ty1 - ty0);
        const float* ctp = d_gct + ((size_t)b * MAXT + t) * MAXA + tilebase;

        // reset per-target running top lists (sentinels)
        if (lane < KC) {
            stcv[w][lane] = FLT_MAX; stci[w][lane] = 0x7fffffff;
            stiv[w][lane] = -1.f;
        }
        __syncwarp();

        float thv = FLT_MAX, thI = 0.f;
        int thi = 0x7fffffff, nbc = 0, nbi = 0;

        for (int it = 0; it < iters; it++) {
            int i = it * 32 + lane;
            bool valid = i < nvalid;
            int ii = valid ? i : (nvalid - 1);
            float4 bx = sbox[ii];
            float4 mt = smeta[ii];
            float  ct = ctp[ii];
            float xc = mt.x, yc = mt.y, rad = mt.z;
            int aidx = __float_as_int(mt.w);

            bool inB = fminf(fminf(xc - tx0, yc - ty0), fminf(tx1 - xc, ty1 - yc)) > 0.f;
            bool inC = fmaxf(fabsf(xc - cxt), fabsf(yc - cyt)) < rad;

            float lx = fmaxf(tx0, bx.x), ly = fmaxf(ty0, bx.y);
            float rx = fminf(tx1, bx.z), ry = fminf(ty1, bx.w);
            float ww = fmaxf(rx - lx, 0.f), hh = fmaxf(ry - ly, 0.f);
            float inter = ww * hh;
            float areaP = (bx.z - bx.x) * (bx.w - bx.y);
            float uni = areaT + areaP - inter;
            float iou = inter / fmaxf(uni, 1e-9f);

            float cost = ct - 3.0f * __log2f(iou + 1e-8f);
            if (!(inB && inC)) cost += PEN2;

            bool pI = valid && (iou > thI);
            unsigned mi = __ballot_sync(0xffffffffu, pI);
            if (mi) {
                int cnt = __popc(mi);
                if (nbi + cnt > BUFCAP) {
                    if (lane < KC) sbiv[w][nbi + lane] = stiv[w][lane];
                    __syncwarp();
                    sel_iou(sbiv[w], nbi + KC, stiv[w], lane);
                    thI = fmaxf(stiv[w][KC - 1], 0.f);
                    nbi = 0;
                    pI = valid && (iou > thI);
                    mi = __ballot_sync(0xffffffffu, pI);
                    cnt = __popc(mi);
                }
                if (pI) sbiv[w][nbi + __popc(mi & ((1u << lane) - 1u))] = iou;
                nbi += cnt;
            }

            bool pC = valid && (cost < thv || (cost == thv && aidx < thi));
            unsigned mc = __ballot_sync(0xffffffffu, pC);
            if (mc) {
                int cnt = __popc(mc);
                if (nbc + cnt > BUFCAP) {
                    if (lane < KC) { sbcv[w][nbc + lane] = stcv[w][lane]; sbci[w][nbc + lane] = stci[w][lane]; }
                    __syncwarp();
                    sel_cost(sbcv[w], sbci[w], nbc + KC, stcv[w], stci[w], lane);
                    thv = stcv[w][KC - 1]; thi = stci[w][KC - 1];
                    nbc = 0;
                    pC = valid && (cost < thv || (cost == thv && aidx < thi));
                    mc = __ballot_sync(0xffffffffu, pC);
                    cnt = __popc(mc);
                }
                if (pC) {
                    int sl = nbc + __popc(mc & ((1u << lane) - 1u));
                    sbcv[w][sl] = cost; sbci[w][sl] = aidx;
                }
                nbc += cnt;
            }
        }
        __syncwarp();

        // dump buffer + running top-10 (no selection): union covers tile top-10
        int pb = (b * MAXT + t) * NCHK + chunk;
        int totc = nbc + KC;
        for (int s = lane; s < totc; s += 32) {
            float v; int idv;
            if (s < nbc) { v = sbcv[w][s]; idv = sbci[w][s]; }
            else         { v = stcv[w][s - nbc]; idv = stci[w][s - nbc]; }
            d_pcv[pb][s] = v; d_pci[pb][s] = idv;
        }
        int toti = nbi + KC;
        for (int s = lane; s < toti; s += 32) {
            d_piv[pb][s] = (s < nbi) ? sbiv[w][s] : stiv[w][s - nbi];
        }
        if (lane == 0) { d_pcn[pb] = totc; d_pin[pb] = toti; }
        __syncwarp();
    }
}

// K2b: block per (b,t). Gather dumps, exact top-10 cost + top-10 iou,
// dyn_k, commit atomics + match list.
__global__ __launch_bounds__(256) void k2b_merge(int A, int T)
{
    __shared__ float scv[NCHK * PCAP]; __shared__ int sci[NCHK * PCAP];
    __shared__ float siv[NCHK * PCAP];
    __shared__ int soffc[NCHK + 1], soffi[NCHK + 1];
    __shared__ float topv[KC]; __shared__ int topi[KC];
    __shared__ float tpiv[KC];
    __shared__ int sdk;

    int bt = blockIdx.x;
    int b = bt / T, t = bt - b * T;
    int N = d_cnt[b];
    int nchk = min(NCHK, (N + TILE - 1) / TILE);
    int tid = threadIdx.x;
    int pbase = (b * MAXT + t) * NCHK;

    if (tid == 0) {
        int oc = 0, oi = 0;
        for (int c = 0; c < nchk; c++) {
            soffc[c] = oc; oc += d_pcn[pbase + c];
            soffi[c] = oi; oi += d_pin[pbase + c];
        }
        soffc[nchk] = oc; soffi[nchk] = oi;
    }
    __syncthreads();
    int totc = soffc[nchk], toti = soffi[nchk];

    for (int c = 0; c < nchk; c++) {
        int nc = soffc[c + 1] - soffc[c];
        if (tid < nc) {
            scv[soffc[c] + tid] = d_pcv[pbase + c][tid];
            sci[soffc[c] + tid] = d_pci[pbase + c][tid];
        }
        int ni = soffi[c + 1] - soffi[c];
        if (tid < ni) siv[soffi[c] + tid] = d_piv[pbase + c][tid];
    }
    __syncthreads();

    int w = tid >> 5, lane = tid & 31;
    if (w == 0) {
        sel_cost(scv, sci, totc, topv, topi, lane);
    } else if (w == 1) {
        sel_iou(siv, toti, tpiv, lane);
        if (lane == 0) {
            float s = 0.f;
            #pragma unroll
            for (int r = 0; r < KC; r++) { float v = tpiv[r]; if (v > 0.f) s += v; }
            int dk = (int)s;
            sdk = max(1, min(KC, dk));
        }
    }
    __syncthreads();

    if (tid < KC && tid < sdk) {
        int id = topi[tid];
        if (id != 0x7fffffff) {
            int old = atomicAdd(&d_count[b * A + id], 1);
            atomicMin(&d_mint[b * A + id], t);
            if (old == 0) {
                int p = atomicAdd(&d_mcnt[b], 1);
                d_mlist[b][p] = id;
            }
        }
    }
}

// K4a: streaming default fill (mm=0, box=0, obj=0, cls=80)
__global__ __launch_bounds__(256) void k4a_fill(float* __restrict__ out, int BA)
{
    int n = blockIdx.x * 256 + threadIdx.x;
    int tot = (7 * BA) >> 2;
    if (n < tot) {
        float4 v = (n >= ((6 * BA) >> 2)) ? make_float4(80.f, 80.f, 80.f, 80.f)
                                          : make_float4(0.f, 0.f, 0.f, 0.f);
        ((float4*)out)[n] = v;
    }
}

// K4b: resolve only matched anchors (from per-image match list)
__global__ __launch_bounds__(512) void k4b_resolve(
    const float* __restrict__ target, float* __restrict__ out,
    int A, int T, int B)
{
    __shared__ float st[MAXT * 5];
    int b = blockIdx.x;
    for (int j = threadIdx.x; j < T * 5; j += 512)
        st[j] = target[(size_t)b * T * 5 + j];
    __syncthreads();

    int m = d_mcnt[b];
    int BA = B * A;
    for (int j = threadIdx.x; j < m; j += 512) {
        int id  = d_mlist[b][j];
        int gi  = b * A + id;
        int c   = d_count[gi];
        int pos = d_pos[gi];
        float4 bx = d_gbox[b][pos];
        float4 mt = d_gmeta[b][pos];
        float xc = mt.x, yc = mt.y, rad = mt.z;
        float areaP = (bx.z - bx.x) * (bx.w - bx.y);
        const float* gct = d_gct + (size_t)b * MAXT * MAXA + pos;

        float maxiou = 0.f, bestC = FLT_MAX;
        int bestT = 0;
        bool conflict = (c > 1);

        for (int t = 0; t < T; t++) {
            float tx0 = st[t * 5 + 1], ty0 = st[t * 5 + 2];
            float tx1 = st[t * 5 + 3], ty1 = st[t * 5 + 4];
            float lx = fmaxf(tx0, bx.x), ly = fmaxf(ty0, bx.y);
            float rx = fminf(tx1, bx.z), ry = fminf(ty1, bx.w);
            float w2 = fmaxf(rx - lx, 0.f), h2 = fmaxf(ry - ly, 0.f);
            float inter = w2 * h2;
            float areaT = (tx1 - tx0) * (ty1 - ty0);
            float uni = areaT + areaP - inter;
            float iou = inter / fmaxf(uni, 1e-9f);
            maxiou = fmaxf(maxiou, iou);
            if (conflict) {
                float cx = 0.5f * (tx0 + tx1), cy = 0.5f * (ty0 + ty1);
                bool inB = fminf(fminf(xc - tx0, yc - ty0), fminf(tx1 - xc, ty1 - yc)) > 0.f;
                bool inC = fmaxf(fabsf(xc - cx), fabsf(yc - cy)) < rad;
                float cost = gct[(size_t)t * MAXA] - 3.0f * __log2f(iou + 1e-8f);
                if (!(inB && inC)) cost += PEN2;
                if (cost < bestC) { bestC = cost; bestT = t; }
            }
        }

        int tt = conflict ? bestT : d_mint[gi];
        out[gi] = 1.f;
        ((float4*)(out + BA))[gi] = make_float4(st[tt * 5 + 1], st[tt * 5 + 2],
                                                st[tt * 5 + 3], st[tt * 5 + 4]);
        out[(size_t)5 * BA + gi] = maxiou;
        out[(size_t)6 * BA + gi] = st[tt * 5 + 0];
    }
}

extern "C" void kernel_launch(void* const* d_in, const int* in_sizes, int n_in,
                              void* d_out, int out_size)
{
    const float* pred    = (const float*)d_in[0];
    const float* target  = (const float*)d_in[1];
    const float* grid    = (const float*)d_in[2];
    const float* stridem = (const float*)d_in[3];

    int A = in_sizes[3];
    int B = in_sizes[0] / (A * 84);
    int T = in_sizes[1] / (B * 5);
    int BA = B * A;

    k0a_zero<<<1, 32>>>();
    k0b_zero<<<1, 32>>>();

    dim3 g1((A + 127) / 128, B);
    k1_anchor<<<g1, 128>>>(pred, target, grid, stridem, A, T);

    dim3 g2a(NCHK, B);
    k2a_scan<<<g2a, 256>>>(target, A, T);      // profiler slot 4

    k2b_merge<<<B * T, 256>>>(A, T);

    int tot4 = (7 * BA) / 4;
    k4a_fill<<<(tot4 + 255) / 256, 256>>>((float*)d_out, BA);

    k4b_resolve<<<B, 512>>>(target, (float*)d_out, A, T, B);
}

// round 8
// speedup vs baseline: 1.3020x; 1.3020x over previous
#include <cuda_runtime.h>
#include <cuda_fp16.h>
#include <math.h>
#include <float.h>

#define MAXB 16
#define MAXA 33600
#define MAXT 50
#define NCLS 80
#define KC 10
#define NSPL 4
#define BUFCAP 64
#define BUFTOT 80
#define INV_LN2 1.4426950408889634f
#define PEN2 (100000.0f * 1.4426950408889634f)

// Scratch (static __device__ globals)
__device__ int    d_cnt [MAXB];
__device__ int    d_mcnt[MAXB];
__device__ int    d_mlist[MAXB][MAXT * KC + 32];
__device__ float4 d_gbox [MAXB][MAXA];
__device__ uint2  d_gmeta8[MAXB][MAXA];          // half2(xc,yc) | aidx | half(rad)
__device__ float  d_gct  [MAXB * MAXT * MAXA];   // [b][t][pos] coalesced
__device__ int    d_pos  [MAXB * MAXA];
__device__ int    d_count[MAXB * MAXA];
__device__ int    d_mint [MAXB * MAXA];
// k2a -> k2b per-chunk exact top-10 dumps
__device__ float  d_dcv[MAXB * MAXT * NSPL][KC];
__device__ int    d_dci[MAXB * MAXT * NSPL][KC];
__device__ float  d_div[MAXB * MAXT * NSPL][KC];

__global__ void k0a_zero() {
    if (threadIdx.x < MAXB) d_cnt[threadIdx.x] = 0;
}
__global__ void k0b_zero() {
    if (threadIdx.x < MAXB) d_mcnt[threadIdx.x] = 0;
}

// ---------- warp-parallel selection helpers ----------
__device__ __forceinline__ void sel_cost(float* bufv, int* bufi, int total,
                                         float* topv, int* topi, int lane)
{
    int rounds = min(KC, total);
    for (int r = 0; r < rounds; r++) {
        float v = FLT_MAX; int id = 0x7fffffff; int sl = 0;
        for (int s = lane; s < total; s += 32) {
            float vv = bufv[s]; int ii = bufi[s];
            if (vv < v || (vv == v && ii < id)) { v = vv; id = ii; sl = s; }
        }
        #pragma unroll
        for (int off = 16; off; off >>= 1) {
            float ov = __shfl_xor_sync(0xffffffffu, v, off);
            int   oi = __shfl_xor_sync(0xffffffffu, id, off);
            int   os = __shfl_xor_sync(0xffffffffu, sl, off);
            if (ov < v || (ov == v && oi < id)) { v = ov; id = oi; sl = os; }
        }
        if (lane == 0) { topv[r] = v; topi[r] = id; bufv[sl] = FLT_MAX; bufi[sl] = 0x7fffffff; }
        __syncwarp();
    }
    if (lane >= rounds && lane < KC) { topv[lane] = FLT_MAX; topi[lane] = 0x7fffffff; }
    __syncwarp();
}

__device__ __forceinline__ void sel_iou(float* bufv, int total, float* topv, int lane)
{
    int rounds = min(KC, total);
    for (int r = 0; r < rounds; r++) {
        float v = -1.f; int sl = 0;
        for (int s = lane; s < total; s += 32) {
            float vv = bufv[s];
            if (vv > v) { v = vv; sl = s; }
        }
        #pragma unroll
        for (int off = 16; off; off >>= 1) {
            float ov = __shfl_xor_sync(0xffffffffu, v, off);
            int   os = __shfl_xor_sync(0xffffffffu, sl, off);
            if (ov > v) { v = ov; sl = os; }
        }
        if (lane == 0) { topv[r] = v; bufv[sl] = -1.f; }
        __syncwarp();
    }
    if (lane >= rounds && lane < KC) topv[lane] = -1.f;
    __syncwarp();
}

// K1: per-anchor. S2 = softplus-sum/ln2, iba flags, compaction.
__global__ __launch_bounds__(128) void k1_anchor(
    const float* __restrict__ pred, const float* __restrict__ target,
    const float* __restrict__ grid, const float* __restrict__ stridem,
    int A, int T)
{
    __shared__ float sp[128 * 85];
    __shared__ float st[MAXT * 8];
    __shared__ int   scls[MAXT];

    int b    = blockIdx.y;
    int base = blockIdx.x * 128;
    int nrows = min(128, A - base);

    const float* predb = pred + ((size_t)b * A + base) * 84;
    for (int i = threadIdx.x; i < nrows * 84; i += 128) {
        int r = i / 84;
        int c = i - r * 84;
        sp[r * 85 + c] = predb[i];
    }
    for (int i = threadIdx.x; i < T; i += 128) {
        const float* tg = target + ((size_t)b * T + i) * 5;
        float cl = tg[0], x0 = tg[1], y0 = tg[2], x1 = tg[3], y1 = tg[4];
        st[i * 8 + 0] = x0; st[i * 8 + 1] = y0;
        st[i * 8 + 2] = x1; st[i * 8 + 3] = y1;
        st[i * 8 + 4] = 0.5f * (x0 + x1);
        st[i * 8 + 5] = 0.5f * (y0 + y1);
        scls[i] = (int)cl;
    }
    __syncthreads();

    int tid  = threadIdx.x;
    int lane = tid & 31;
    bool alive = (tid < nrows);
    int a = base + tid;

    bool iba = false;
    float S2 = 0.f, px0 = 0, py0 = 0, px1 = 0, py1 = 0, xc = 0, yc = 0, rad = 0;
    const float* row = sp + tid * 85;

    if (alive) {
        float strv = stridem[a];
        xc  = (grid[2 * a]     + 0.5f) * strv;
        yc  = (grid[2 * a + 1] + 0.5f) * strv;
        rad = 2.5f * strv;
        px0 = row[0]; py0 = row[1]; px1 = row[2]; py1 = row[3];

        float P = 1.f;
        int   E = 0;
        #pragma unroll 4
        for (int c = 0; c < NCLS; c++) {
            float e = __expf(row[4 + c]);
            P *= (1.f + e);
            if ((c & 3) == 3) {
                int bits = __float_as_int(P);
                E += ((bits >> 23) & 255) - 127;
                P = __int_as_float((bits & 0x007FFFFF) | 0x3F800000);
            }
        }
        S2 = (float)E + __log2f(P);

        bool anyB = false, anyC = false;
        for (int t = 0; t < T; t++) {
            float tx0 = st[t * 8 + 0], ty0 = st[t * 8 + 1];
            float tx1 = st[t * 8 + 2], ty1 = st[t * 8 + 3];
            float cxt = st[t * 8 + 4], cyt = st[t * 8 + 5];
            bool inB = fminf(fminf(xc - tx0, yc - ty0), fminf(tx1 - xc, ty1 - yc)) > 0.f;
            bool inC = fmaxf(fabsf(xc - cxt), fabsf(yc - cyt)) < rad;
            anyB |= inB; anyC |= inC;
        }
        iba = anyB || anyC;
    }

    unsigned m = __ballot_sync(0xffffffffu, iba);
    if (m) {
        int leader = __ffs(m) - 1;
        int wbase = 0;
        if (lane == leader) wbase = atomicAdd(&d_cnt[b], __popc(m));
        wbase = __shfl_sync(0xffffffffu, wbase, leader);
        if (iba) {
            int pos = wbase + __popc(m & ((1u << lane) - 1u));
            int gi = b * A + a;
            d_pos  [gi] = pos;
            d_count[gi] = 0;
            d_mint [gi] = 0x7fffffff;
            d_gbox [b][pos] = make_float4(px0, py0, px1, py1);
            __half2 hxy = __floats2half2_rn(xc, yc);
            unsigned short hr = __half_as_ushort(__float2half_rn(rad));
            uint2 u;
            u.x = *reinterpret_cast<unsigned*>(&hxy);
            u.y = (unsigned)a | ((unsigned)hr << 16);
            d_gmeta8[b][pos] = u;
            float* gct = d_gct + (size_t)b * MAXT * MAXA + pos;
            for (int t = 0; t < T; t++)
                gct[(size_t)t * MAXA] = S2 - row[4 + scls[t]] * INV_LN2;
        }
    }
}

// K2a: block per (t, chunk, b). 256 threads lane-split over the chunk's
// candidate range; persistent threshold filter; in-block exact top-10 merge;
// dump 10+10 entries per chunk.
__global__ __launch_bounds__(256) void k2a_scan(
    const float* __restrict__ target, int A, int T)
{
    __shared__ float sbcv[8][BUFTOT]; __shared__ int sbci[8][BUFTOT];
    __shared__ float sbiv[8][BUFTOT];
    __shared__ float stcv[8][KC];     __shared__ int stci[8][KC];
    __shared__ float stiv[8][KC];
    __shared__ float smcv[KC];        __shared__ int smci[KC];
    __shared__ float smiv[KC];

    int t     = blockIdx.x;
    int chunk = blockIdx.y;
    int b     = blockIdx.z;
    int w = threadIdx.x >> 5, lane = threadIdx.x & 31;
    int N = d_cnt[b];
    int lo = (chunk * N) / NSPL;
    int hi = ((chunk + 1) * N) / NSPL;

    if (lane < KC) {
        stcv[w][lane] = FLT_MAX; stci[w][lane] = 0x7fffffff;
        stiv[w][lane] = -1.f;
    }
    __syncwarp();

    const float* tg = target + ((size_t)b * T + t) * 5;
    float tx0 = tg[1], ty0 = tg[2], tx1 = tg[3], ty1 = tg[4];
    float cxt = 0.5f * (tx0 + tx1), cyt = 0.5f * (ty0 + ty1);
    float areaT = (tx1 - tx0) * (ty1 - ty0);
    const float* gct = d_gct + ((size_t)b * MAXT + t) * MAXA;

    float thv = FLT_MAX; int thi = 0x7fffffff; int nbc = 0;
    float thI = 0.f;                             int nbi = 0;

    for (int basei = lo; basei < hi; basei += 256) {
        int i = basei + threadIdx.x;
        bool valid = i < hi;
        int ii = valid ? i : (hi - 1);
        float4 bx = d_gbox[b][ii];
        uint2  mg = d_gmeta8[b][ii];
        float  ct = gct[ii];
        __half2 hxy = *reinterpret_cast<__half2*>(&mg.x);
        float xc = __low2float(hxy), yc = __high2float(hxy);
        int aidx = (int)(mg.y & 0xffffu);
        float rad = __half2float(__ushort_as_half((unsigned short)(mg.y >> 16)));

        bool inB = fminf(fminf(xc - tx0, yc - ty0), fminf(tx1 - xc, ty1 - yc)) > 0.f;
        bool inC = fmaxf(fabsf(xc - cxt), fabsf(yc - cyt)) < rad;

        float lx = fmaxf(tx0, bx.x), ly = fmaxf(ty0, bx.y);
        float rx = fminf(tx1, bx.z), ry = fminf(ty1, bx.w);
        float ww = fmaxf(rx - lx, 0.f), hh = fmaxf(ry - ly, 0.f);
        float inter = ww * hh;
        float areaP = (bx.z - bx.x) * (bx.w - bx.y);
        float uni = areaT + areaP - inter;
        float iou = inter / fmaxf(uni, 1e-9f);

        float cost = ct - 3.0f * __log2f(iou + 1e-8f);
        if (!(inB && inC)) cost += PEN2;

        bool pI = valid && (iou > thI);
        unsigned mi = __ballot_sync(0xffffffffu, pI);
        if (mi) {
            int cnt = __popc(mi);
            if (nbi + cnt > BUFCAP) {
                if (lane < KC) sbiv[w][nbi + lane] = stiv[w][lane];
                __syncwarp();
                sel_iou(sbiv[w], nbi + KC, stiv[w], lane);
                thI = fmaxf(stiv[w][KC - 1], 0.f);
                nbi = 0;
                pI = valid && (iou > thI);
                mi = __ballot_sync(0xffffffffu, pI);
                cnt = __popc(mi);
            }
            if (pI) sbiv[w][nbi + __popc(mi & ((1u << lane) - 1u))] = iou;
            nbi += cnt;
        }

        bool pC = valid && (cost < thv || (cost == thv && aidx < thi));
        unsigned mc = __ballot_sync(0xffffffffu, pC);
        if (mc) {
            int cnt = __popc(mc);
            if (nbc + cnt > BUFCAP) {
                if (lane < KC) { sbcv[w][nbc + lane] = stcv[w][lane]; sbci[w][nbc + lane] = stci[w][lane]; }
                __syncwarp();
                sel_cost(sbcv[w], sbci[w], nbc + KC, stcv[w], stci[w], lane);
                thv = stcv[w][KC - 1]; thi = stci[w][KC - 1];
                nbc = 0;
                pC = valid && (cost < thv || (cost == thv && aidx < thi));
                mc = __ballot_sync(0xffffffffu, pC);
                cnt = __popc(mc);
            }
            if (pC) {
                int sl = nbc + __popc(mc & ((1u << lane) - 1u));
                sbcv[w][sl] = cost; sbci[w][sl] = aidx;
            }
            nbc += cnt;
        }
    }

    // final per-warp flushes
    if (lane < KC) sbiv[w][nbi + lane] = stiv[w][lane];
    __syncwarp();
    sel_iou(sbiv[w], nbi + KC, stiv[w], lane);
    if (lane < KC) { sbcv[w][nbc + lane] = stcv[w][lane]; sbci[w][nbc + lane] = stci[w][lane]; }
    __syncwarp();
    sel_cost(sbcv[w], sbci[w], nbc + KC, stcv[w], stci[w], lane);
    __syncthreads();

    // cross-warp merges (warp0: cost; warp1: iou)
    if (w == 0) {
        sel_cost(&stcv[0][0], &stci[0][0], 8 * KC, smcv, smci, lane);
    } else if (w == 1) {
        sel_iou(&stiv[0][0], 8 * KC, smiv, lane);
    }
    __syncthreads();

    // dump exact per-chunk top-10s
    int pb = (b * MAXT + t) * NSPL + chunk;
    if (threadIdx.x < KC) {
        d_dcv[pb][threadIdx.x] = smcv[threadIdx.x];
        d_dci[pb][threadIdx.x] = smci[threadIdx.x];
        d_div[pb][threadIdx.x] = smiv[threadIdx.x];
    }
}

// K2b: block per (b,t). Merge NSPL chunk top-10s -> exact global top-10,
// dyn_k, commit atomics + match list.
__global__ __launch_bounds__(64) void k2b_merge(int A, int T)
{
    __shared__ float scv[NSPL * KC]; __shared__ int sci[NSPL * KC];
    __shared__ float siv[NSPL * KC];
    __shared__ float topv[KC]; __shared__ int topi[KC];
    __shared__ float tpiv[KC];
    __shared__ int sdk;

    int bt = blockIdx.x;
    int b = bt / T, t = bt - b * T;
    int tid = threadIdx.x;
    int pbase = (b * MAXT + t) * NSPL;

    if (tid < NSPL * KC) {
        int c = tid / KC, r = tid - c * KC;
        scv[tid] = d_dcv[pbase + c][r];
        sci[tid] = d_dci[pbase + c][r];
        siv[tid] = d_div[pbase + c][r];
    }
    __syncthreads();

    int w = tid >> 5, lane = tid & 31;
    if (w == 0) {
        sel_cost(scv, sci, NSPL * KC, topv, topi, lane);
    } else {
        sel_iou(siv, NSPL * KC, tpiv, lane);
        if (lane == 0) {
            float s = 0.f;
            #pragma unroll
            for (int r = 0; r < KC; r++) { float v = tpiv[r]; if (v > 0.f) s += v; }
            int dk = (int)s;
            sdk = max(1, min(KC, dk));
        }
    }
    __syncthreads();

    if (tid < KC && tid < sdk) {
        int id = topi[tid];
        if (id != 0x7fffffff) {
            int old = atomicAdd(&d_count[b * A + id], 1);
            atomicMin(&d_mint[b * A + id], t);
            if (old == 0) {
                int p = atomicAdd(&d_mcnt[b], 1);
                d_mlist[b][p] = id;
            }
        }
    }
}

// K4a: streaming default fill (mm=0, box=0, obj=0, cls=80)
__global__ __launch_bounds__(256) void k4a_fill(float* __restrict__ out, int BA)
{
    int n = blockIdx.x * 256 + threadIdx.x;
    int tot = (7 * BA) >> 2;
    if (n < tot) {
        float4 v = (n >= ((6 * BA) >> 2)) ? make_float4(80.f, 80.f, 80.f, 80.f)
                                          : make_float4(0.f, 0.f, 0.f, 0.f);
        ((float4*)out)[n] = v;
    }
}

// K4b: resolve only matched anchors (from per-image match list)
__global__ __launch_bounds__(512) void k4b_resolve(
    const float* __restrict__ target, float* __restrict__ out,
    int A, int T, int B)
{
    __shared__ float st[MAXT * 5];
    int b = blockIdx.x;
    for (int j = threadIdx.x; j < T * 5; j += 512)
        st[j] = target[(size_t)b * T * 5 + j];
    __syncthreads();

    int m = d_mcnt[b];
    int BA = B * A;
    for (int j = threadIdx.x; j < m; j += 512) {
        int id  = d_mlist[b][j];
        int gi  = b * A + id;
        int c   = d_count[gi];
        int pos = d_pos[gi];
        float4 bx = d_gbox[b][pos];
        uint2  mg = d_gmeta8[b][pos];
        __half2 hxy = *reinterpret_cast<__half2*>(&mg.x);
        float xc = __low2float(hxy), yc = __high2float(hxy);
        float rad = __half2float(__ushort_as_half((unsigned short)(mg.y >> 16)));
        float areaP = (bx.z - bx.x) * (bx.w - bx.y);
        const float* gct = d_gct + (size_t)b * MAXT * MAXA + pos;

        float maxiou = 0.f, bestC = FLT_MAX;
        int bestT = 0;
        bool conflict = (c > 1);

        for (int t = 0; t < T; t++) {
            float tx0 = st[t * 5 + 1], ty0 = st[t * 5 + 2];
            float tx1 = st[t * 5 + 3], ty1 = st[t * 5 + 4];
            float lx = fmaxf(tx0, bx.x), ly = fmaxf(ty0, bx.y);
            float rx = fminf(tx1, bx.z), ry = fminf(ty1, bx.w);
            float w2 = fmaxf(rx - lx, 0.f), h2 = fmaxf(ry - ly, 0.f);
            float inter = w2 * h2;
            float areaT = (tx1 - tx0) * (ty1 - ty0);
            float uni = areaT + areaP - inter;
            float iou = inter / fmaxf(uni, 1e-9f);
            maxiou = fmaxf(maxiou, iou);
            if (conflict) {
                float cx = 0.5f * (tx0 + tx1), cy = 0.5f * (ty0 + ty1);
                bool inB = fminf(fminf(xc - tx0, yc - ty0), fminf(tx1 - xc, ty1 - yc)) > 0.f;
                bool inC = fmaxf(fabsf(xc - cx), fabsf(yc - cy)) < rad;
                float cost = gct[(size_t)t * MAXA] - 3.0f * __log2f(iou + 1e-8f);
                if (!(inB && inC)) cost += PEN2;
                if (cost < bestC) { bestC = cost; bestT = t; }
            }
        }

        int tt = conflict ? bestT : d_mint[gi];
        out[gi] = 1.f;
        ((float4*)(out + BA))[gi] = make_float4(st[tt * 5 + 1], st[tt * 5 + 2],
                                                st[tt * 5 + 3], st[tt * 5 + 4]);
        out[(size_t)5 * BA + gi] = maxiou;
        out[(size_t)6 * BA + gi] = st[tt * 5 + 0];
    }
}

extern "C" void kernel_launch(void* const* d_in, const int* in_sizes, int n_in,
                              void* d_out, int out_size)
{
    const float* pred    = (const float*)d_in[0];
    const float* target  = (const float*)d_in[1];
    const float* grid    = (const float*)d_in[2];
    const float* stridem = (const float*)d_in[3];

    int A = in_sizes[3];
    int B = in_sizes[0] / (A * 84);
    int T = in_sizes[1] / (B * 5);
    int BA = B * A;

    k0a_zero<<<1, 32>>>();
    k0b_zero<<<1, 32>>>();

    dim3 g1((A + 127) / 128, B);
    k1_anchor<<<g1, 128>>>(pred, target, grid, stridem, A, T);

    dim3 g2a(T, NSPL, B);
    k2a_scan<<<g2a, 256>>>(target, A, T);      // profiler slot 4

    k2b_merge<<<B * T, 64>>>(A, T);

    int tot4 = (7 * BA) / 4;
    k4a_fill<<<(tot4 + 255) / 256, 256>>>((float*)d_out, BA);

    k4b_resolve<<<B, 512>>>(target, (float*)d_out, A, T, B);
}

// round 9
// speedup vs baseline: 2.0955x; 1.6094x over previous
#include <cuda_runtime.h>
#include <cuda_fp16.h>
#include <math.h>
#include <float.h>

#define MAXB 16
#define MAXA 33600
#define MAXT 50
#define NCLS 80
#define KC 10
#define LCAP 80
#define LBUF 96
#define BUFCAP 64
#define BUFTOT 80
#define INV_LN2 1.4426950408889634f
#define PEN2 (100000.0f * 1.4426950408889634f)

// Scratch (static __device__ globals)
__device__ int    d_cnt [MAXB];
__device__ int    d_mcnt[MAXB];
__device__ int    d_mlist[MAXB][MAXT * KC + 32];
__device__ int    d_tlen[MAXB * MAXT];
__device__ int    d_tlist[MAXB * MAXT][LCAP];
__device__ float4 d_gbox [MAXB][MAXA];
__device__ uint2  d_gmeta8[MAXB][MAXA];          // half2(xc,yc) | aidx(16b) | half(rad)
__device__ float  d_gS2  [MAXB][MAXA];
__device__ int    d_gaidx[MAXB][MAXA];
__device__ int    d_pos  [MAXB * MAXA];
__device__ int    d_count[MAXB * MAXA];
__device__ int    d_mint [MAXB * MAXA];
__device__ int    d_dk   [MAXB * MAXT];

__global__ void k0a_zero() {
    if (threadIdx.x < MAXB) { d_cnt[threadIdx.x] = 0; d_mcnt[threadIdx.x] = 0; }
}
__global__ void k0b_zero() {
    int i = threadIdx.x;
    if (i < MAXB * MAXT) d_tlen[i] = 0;
}

// ---------- warp-parallel selection helpers ----------
__device__ __forceinline__ void sel_cost(float* bufv, int* bufi, int total,
                                         float* topv, int* topi, int lane)
{
    int rounds = min(KC, total);
    for (int r = 0; r < rounds; r++) {
        float v = FLT_MAX; int id = 0x7fffffff; int sl = 0;
        for (int s = lane; s < total; s += 32) {
            float vv = bufv[s]; int ii = bufi[s];
            if (vv < v || (vv == v && ii < id)) { v = vv; id = ii; sl = s; }
        }
        #pragma unroll
        for (int off = 16; off; off >>= 1) {
            float ov = __shfl_xor_sync(0xffffffffu, v, off);
            int   oi = __shfl_xor_sync(0xffffffffu, id, off);
            int   os = __shfl_xor_sync(0xffffffffu, sl, off);
            if (ov < v || (ov == v && oi < id)) { v = ov; id = oi; sl = os; }
        }
        if (lane == 0) { topv[r] = v; topi[r] = id; bufv[sl] = FLT_MAX; bufi[sl] = 0x7fffffff; }
        __syncwarp();
    }
    if (lane >= rounds && lane < KC) { topv[lane] = FLT_MAX; topi[lane] = 0x7fffffff; }
    __syncwarp();
}

__device__ __forceinline__ void sel_iou(float* bufv, int total, float* topv, int lane)
{
    int rounds = min(KC, total);
    for (int r = 0; r < rounds; r++) {
        float v = -1.f; int sl = 0;
        for (int s = lane; s < total; s += 32) {
            float vv = bufv[s];
            if (vv > v) { v = vv; sl = s; }
        }
        #pragma unroll
        for (int off = 16; off; off >>= 1) {
            float ov = __shfl_xor_sync(0xffffffffu, v, off);
            int   os = __shfl_xor_sync(0xffffffffu, sl, off);
            if (ov > v) { v = ov; sl = os; }
        }
        if (lane == 0) { topv[r] = v; bufv[sl] = -1.f; }
        __syncwarp();
    }
    if (lane >= rounds && lane < KC) topv[lane] = -1.f;
    __syncwarp();
}

// K1: per-anchor. Flags + per-target lists first; softplus S2 only for
// candidate warps; compaction (no ct rows anymore).
__global__ __launch_bounds__(128) void k1_anchor(
    const float* __restrict__ pred, const float* __restrict__ target,
    const float* __restrict__ grid, const float* __restrict__ stridem,
    int A, int T)
{
    __shared__ float sp[128 * 85];
    __shared__ float st[MAXT * 8];

    int b    = blockIdx.y;
    int base = blockIdx.x * 128;
    int nrows = min(128, A - base);

    const float* predb = pred + ((size_t)b * A + base) * 84;
    for (int i = threadIdx.x; i < nrows * 84; i += 128) {
        int r = i / 84;
        int c = i - r * 84;
        sp[r * 85 + c] = predb[i];
    }
    for (int i = threadIdx.x; i < T; i += 128) {
        const float* tg = target + ((size_t)b * T + i) * 5;
        float x0 = tg[1], y0 = tg[2], x1 = tg[3], y1 = tg[4];
        st[i * 8 + 0] = x0; st[i * 8 + 1] = y0;
        st[i * 8 + 2] = x1; st[i * 8 + 3] = y1;
        st[i * 8 + 4] = 0.5f * (x0 + x1);
        st[i * 8 + 5] = 0.5f * (y0 + y1);
    }
    __syncthreads();

    int tid  = threadIdx.x;
    int lane = tid & 31;
    bool alive = (tid < nrows);
    int a = base + tid;

    bool iba = false;
    float px0 = 0, py0 = 0, px1 = 0, py1 = 0, xc = 0, yc = 0, rad = 0;
    const float* row = sp + tid * 85;

    if (alive) {
        float strv = stridem[a];
        xc  = (grid[2 * a]     + 0.5f) * strv;
        yc  = (grid[2 * a + 1] + 0.5f) * strv;
        rad = 2.5f * strv;
        px0 = row[0]; py0 = row[1]; px1 = row[2]; py1 = row[3];
    }

    bool anyB = false, anyC = false;
    for (int t = 0; t < T; t++) {
        bool inB = false, inC = false;
        if (alive) {
            float tx0 = st[t * 8 + 0], ty0 = st[t * 8 + 1];
            float tx1 = st[t * 8 + 2], ty1 = st[t * 8 + 3];
            float cxt = st[t * 8 + 4], cyt = st[t * 8 + 5];
            inB = fminf(fminf(xc - tx0, yc - ty0), fminf(tx1 - xc, ty1 - yc)) > 0.f;
            inC = fmaxf(fabsf(xc - cxt), fabsf(yc - cyt)) < rad;
            anyB |= inB; anyC |= inC;
        }
        // per-target candidate list append (in_box && in_center)
        unsigned mb = __ballot_sync(0xffffffffu, inB && inC);
        if (mb) {
            int bt = b * T + t;
            int leader = __ffs(mb) - 1;
            int wb = 0;
            if (lane == leader) wb = atomicAdd(&d_tlen[bt], __popc(mb));
            wb = __shfl_sync(0xffffffffu, wb, leader);
            if (inB && inC) {
                int slot = wb + __popc(mb & ((1u << lane) - 1u));
                if (slot < LCAP) d_tlist[bt][slot] = a;
            }
        }
    }
    iba = alive && (anyB || anyC);

    unsigned m = __ballot_sync(0xffffffffu, iba);
    if (m) {
        float S2 = 0.f;
        if (iba) {
            float P = 1.f;
            int   E = 0;
            #pragma unroll 4
            for (int c = 0; c < NCLS; c++) {
                float e = __expf(row[4 + c]);
                P *= (1.f + e);
                if ((c & 3) == 3) {
                    int bits = __float_as_int(P);
                    E += ((bits >> 23) & 255) - 127;
                    P = __int_as_float((bits & 0x007FFFFF) | 0x3F800000);
                }
            }
            S2 = (float)E + __log2f(P);
        }
        int leader = __ffs(m) - 1;
        int wbase = 0;
        if (lane == leader) wbase = atomicAdd(&d_cnt[b], __popc(m));
        wbase = __shfl_sync(0xffffffffu, wbase, leader);
        if (iba) {
            int pos = wbase + __popc(m & ((1u << lane) - 1u));
            int gi = b * A + a;
            d_pos  [gi] = pos;
            d_count[gi] = 0;
            d_mint [gi] = 0x7fffffff;
            d_gbox [b][pos] = make_float4(px0, py0, px1, py1);
            __half2 hxy = __floats2half2_rn(xc, yc);
            unsigned short hr = __half_as_ushort(__float2half_rn(rad));
            uint2 u;
            u.x = *reinterpret_cast<unsigned*>(&hxy);
            u.y = (unsigned)(a & 0xffff) | ((unsigned)hr << 16);
            d_gmeta8[b][pos] = u;
            d_gS2  [b][pos] = S2;
            d_gaidx[b][pos] = a;
        }
    }
}

// K2a: iou top-10 + dyn_k per (b,t). Block = 4 warps, each scans a quarter
// of the candidates with a division-free conservative screen; exact IEEE iou
// only for pushed (rare) lanes. Block merge -> dk.
__global__ __launch_bounds__(128) void k2a_iou(
    const float* __restrict__ target, int A, int T)
{
    __shared__ float sbiv[4][BUFTOT];
    __shared__ float stiv[4][KC];
    __shared__ float tpv[KC];

    int t = blockIdx.x, b = blockIdx.y;
    int w = threadIdx.x >> 5, lane = threadIdx.x & 31;
    int N = d_cnt[b];
    int lo = (w * N) >> 2;
    int hi = ((w + 1) * N) >> 2;

    const float* tg = target + ((size_t)b * T + t) * 5;
    float tx0 = tg[1], ty0 = tg[2], tx1 = tg[3], ty1 = tg[4];
    float areaT = (tx1 - tx0) * (ty1 - ty0);

    if (lane < KC) stiv[w][lane] = -1.f;
    __syncwarp();

    float thI = 0.f, qs = 0.f;
    int nb = 0;

    for (int base = lo; base < hi; base += 32) {
        int i = base + lane;
        bool valid = i < hi;
        int ii = valid ? i : (hi - 1);
        float4 bx = d_gbox[b][ii];
        float lx = fmaxf(tx0, bx.x), ly = fmaxf(ty0, bx.y);
        float rx = fminf(tx1, bx.z), ry = fminf(ty1, bx.w);
        float ww = fmaxf(rx - lx, 0.f), hh = fmaxf(ry - ly, 0.f);
        float inter = ww * hh;
        float areaP = (bx.z - bx.x) * (bx.w - bx.y);
        float areaS = areaT + areaP;

        bool p = valid && (inter > qs * areaS);
        unsigned mk = __ballot_sync(0xffffffffu, p);
        if (mk) {
            int cnt = __popc(mk);
            if (nb + cnt > BUFCAP) {
                if (lane < KC) sbiv[w][nb + lane] = stiv[w][lane];
                __syncwarp();
                sel_iou(sbiv[w], nb + KC, stiv[w], lane);
                thI = fmaxf(stiv[w][KC - 1], 0.f);
                qs = (thI > 0.f) ? __fdividef(thI, 1.f + thI) * (1.f - 1e-5f) : 0.f;
                nb = 0;
                p = valid && (inter > qs * areaS);
                mk = __ballot_sync(0xffffffffu, p);
                cnt = __popc(mk);
            }
            if (p) {
                float uni = areaS - inter;
                float iou = inter / fmaxf(uni, 1e-9f);   // exact IEEE (rare path)
                sbiv[w][nb + __popc(mk & ((1u << lane) - 1u))] = iou;
            }
            nb += cnt;
        }
    }

    if (lane < KC) sbiv[w][nb + lane] = stiv[w][lane];
    __syncwarp();
    sel_iou(sbiv[w], nb + KC, stiv[w], lane);
    __syncthreads();

    if (w == 0) {
        sel_iou(&stiv[0][0], 4 * KC, tpv, lane);
        if (lane == 0) {
            float s = 0.f;
            #pragma unroll
            for (int r = 0; r < KC; r++) { float v = tpv[r]; if (v > 0.f) s += v; }
            int dk = (int)s;
            d_dk[b * T + t] = max(1, min(KC, dk));
        }
    }
}

// K2c: cost top-10 per (b,t) from the per-target list (<=75 entries,
// all unpenalized -> exact). Rare fallback: full scan with penalty.
// Then commit atomics + match list.
__global__ __launch_bounds__(256) void k2c_cost(
    const float* __restrict__ pred, const float* __restrict__ target,
    int A, int T)
{
    __shared__ float bufv[8][LBUF]; __shared__ int bufi[8][LBUF];
    __shared__ float topv[8][KC];   __shared__ int topi[8][KC];

    int w = threadIdx.x >> 5, lane = threadIdx.x & 31;
    int t = blockIdx.x * 8 + w;
    int b = blockIdx.y;
    if (t >= T) return;

    int bt = b * T + t;
    const float* tg = target + ((size_t)b * T + t) * 5;
    int cls = (int)tg[0];
    float tx0 = tg[1], ty0 = tg[2], tx1 = tg[3], ty1 = tg[4];
    float areaT = (tx1 - tx0) * (ty1 - ty0);
    const float* predb = pred + (size_t)b * A * 84;
    int n = d_tlen[bt];

    if (n >= KC) {
        // list path: exact (all entries unpenalized; penalized can't reach top-10)
        int nn = min(n, LCAP);
        for (int s = lane; s < nn; s += 32) {
            int aidx = d_tlist[bt][s];
            int pos = d_pos[b * A + aidx];
            float4 bx = d_gbox[b][pos];
            float S2 = d_gS2[b][pos];
            float z = predb[(size_t)aidx * 84 + 4 + cls];
            float ct = S2 - z * INV_LN2;
            float lx = fmaxf(tx0, bx.x), ly = fmaxf(ty0, bx.y);
            float rx = fminf(tx1, bx.z), ry = fminf(ty1, bx.w);
            float ww = fmaxf(rx - lx, 0.f), hh = fmaxf(ry - ly, 0.f);
            float inter = ww * hh;
            float areaP = (bx.z - bx.x) * (bx.w - bx.y);
            float uni = areaT + areaP - inter;
            float iou = inter / fmaxf(uni, 1e-9f);
            bufv[w][s] = ct - 3.0f * __log2f(iou + 1e-8f);
            bufi[w][s] = aidx;
        }
        __syncwarp();
        sel_cost(bufv[w], bufi[w], nn, topv[w], topi[w], lane);
    } else {
        // fallback: full filtered scan (rare)
        int N = d_cnt[b];
        float cxt = 0.5f * (tx0 + tx1), cyt = 0.5f * (ty0 + ty1);
        if (lane < KC) { topv[w][lane] = FLT_MAX; topi[w][lane] = 0x7fffffff; }
        __syncwarp();
        float thv = FLT_MAX; int thi = 0x7fffffff; int nb = 0;

        for (int base = 0; base < N; base += 32) {
            int i = base + lane;
            bool valid = i < N;
            int ii = valid ? i : (N - 1);
            float4 bx = d_gbox[b][ii];
            uint2  mg = d_gmeta8[b][ii];
            float  S2 = d_gS2[b][ii];
            int  aidx = d_gaidx[b][ii];
            float z = predb[(size_t)aidx * 84 + 4 + cls];
            float ct = S2 - z * INV_LN2;
            __half2 hxy = *reinterpret_cast<__half2*>(&mg.x);
            float xc = __low2float(hxy), yc = __high2float(hxy);
            float rad = __half2float(__ushort_as_half((unsigned short)(mg.y >> 16)));

            bool inB = fminf(fminf(xc - tx0, yc - ty0), fminf(tx1 - xc, ty1 - yc)) > 0.f;
            bool inC = fmaxf(fabsf(xc - cxt), fabsf(yc - cyt)) < rad;
            float lx = fmaxf(tx0, bx.x), ly = fmaxf(ty0, bx.y);
            float rx = fminf(tx1, bx.z), ry = fminf(ty1, bx.w);
            float ww = fmaxf(rx - lx, 0.f), hh = fmaxf(ry - ly, 0.f);
            float inter = ww * hh;
            float areaP = (bx.z - bx.x) * (bx.w - bx.y);
            float uni = areaT + areaP - inter;
            float iou = inter / fmaxf(uni, 1e-9f);
            float cost = ct - 3.0f * __log2f(iou + 1e-8f);
            if (!(inB && inC)) cost += PEN2;

            bool pC = valid && (cost < thv || (cost == thv && aidx < thi));
            unsigned mc = __ballot_sync(0xffffffffu, pC);
            if (mc) {
                int cnt = __popc(mc);
                if (nb + cnt > BUFCAP) {
                    if (lane < KC) { bufv[w][nb + lane] = topv[w][lane]; bufi[w][nb + lane] = topi[w][lane]; }
                    __syncwarp();
                    sel_cost(bufv[w], bufi[w], nb + KC, topv[w], topi[w], lane);
                    thv = topv[w][KC - 1]; thi = topi[w][KC - 1];
                    nb = 0;
                    pC = valid && (cost < thv || (cost == thv && aidx < thi));
                    mc = __ballot_sync(0xffffffffu, pC);
                    cnt = __popc(mc);
                }
                if (pC) {
                    int sl = nb + __popc(mc & ((1u << lane) - 1u));
                    bufv[w][sl] = cost; bufi[w][sl] = aidx;
                }
                nb += cnt;
            }
        }
        if (lane < KC) { bufv[w][nb + lane] = topv[w][lane]; bufi[w][nb + lane] = topi[w][lane]; }
        __syncwarp();
        sel_cost(bufv[w], bufi[w], nb + KC, topv[w], topi[w], lane);
    }

    int dk = d_dk[bt];
    if (lane < dk) {
        int id = topi[w][lane];
        if (id != 0x7fffffff) {
            int old = atomicAdd(&d_count[b * A + id], 1);
            atomicMin(&d_mint[b * A + id], t);
            if (old == 0) {
                int p = atomicAdd(&d_mcnt[b], 1);
                d_mlist[b][p] = id;
            }
        }
    }
}

// K4a: streaming default fill (mm=0, box=0, obj=0, cls=80)
__global__ __launch_bounds__(256) void k4a_fill(float* __restrict__ out, int BA)
{
    int n = blockIdx.x * 256 + threadIdx.x;
    int tot = (7 * BA) >> 2;
    if (n < tot) {
        float4 v = (n >= ((6 * BA) >> 2)) ? make_float4(80.f, 80.f, 80.f, 80.f)
                                          : make_float4(0.f, 0.f, 0.f, 0.f);
        ((float4*)out)[n] = v;
    }
}

// K4b: resolve only matched anchors (from per-image match list)
__global__ __launch_bounds__(512) void k4b_resolve(
    const float* __restrict__ pred, const float* __restrict__ target,
    float* __restrict__ out, int A, int T, int B)
{
    __shared__ float st[MAXT * 5];
    int b = blockIdx.x;
    for (int j = threadIdx.x; j < T * 5; j += 512)
        st[j] = target[(size_t)b * T * 5 + j];
    __syncthreads();

    int m = d_mcnt[b];
    int BA = B * A;
    const float* predb = pred + (size_t)b * A * 84;
    for (int j = threadIdx.x; j < m; j += 512) {
        int id  = d_mlist[b][j];
        int gi  = b * A + id;
        int c   = d_count[gi];
        int pos = d_pos[gi];
        float4 bx = d_gbox[b][pos];
        uint2  mg = d_gmeta8[b][pos];
        float  S2 = d_gS2[b][pos];
        __half2 hxy = *reinterpret_cast<__half2*>(&mg.x);
        float xc = __low2float(hxy), yc = __high2float(hxy);
        float rad = __half2float(__ushort_as_half((unsigned short)(mg.y >> 16)));
        float areaP = (bx.z - bx.x) * (bx.w - bx.y);

        float maxiou = 0.f, bestC = FLT_MAX;
        int bestT = 0;
        bool conflict = (c > 1);

        for (int t = 0; t < T; t++) {
            float tx0 = st[t * 5 + 1], ty0 = st[t * 5 + 2];
            float tx1 = st[t * 5 + 3], ty1 = st[t * 5 + 4];
            float lx = fmaxf(tx0, bx.x), ly = fmaxf(ty0, bx.y);
            float rx = fminf(tx1, bx.z), ry = fminf(ty1, bx.w);
            float w2 = fmaxf(rx - lx, 0.f), h2 = fmaxf(ry - ly, 0.f);
            float inter = w2 * h2;
            float areaT = (tx1 - tx0) * (ty1 - ty0);
            float uni = areaT + areaP - inter;
            float iou = inter / fmaxf(uni, 1e-9f);
            maxiou = fmaxf(maxiou, iou);
            if (conflict) {
                int cls = (int)st[t * 5 + 0];
                float z = predb[(size_t)id * 84 + 4 + cls];
                float ct = S2 - z * INV_LN2;
                float cx = 0.5f * (tx0 + tx1), cy = 0.5f * (ty0 + ty1);
                bool inB = fminf(fminf(xc - tx0, yc - ty0), fminf(tx1 - xc, ty1 - yc)) > 0.f;
                bool inC = fmaxf(fabsf(xc - cx), fabsf(yc - cy)) < rad;
                float cost = ct - 3.0f * __log2f(iou + 1e-8f);
                if (!(inB && inC)) cost += PEN2;
                if (cost < bestC) { bestC = cost; bestT = t; }
            }
        }

        int tt = conflict ? bestT : d_mint[gi];
        out[gi] = 1.f;
        ((float4*)(out + BA))[gi] = make_float4(st[tt * 5 + 1], st[tt * 5 + 2],
                                                st[tt * 5 + 3], st[tt * 5 + 4]);
        out[(size_t)5 * BA + gi] = maxiou;
        out[(size_t)6 * BA + gi] = st[tt * 5 + 0];
    }
}

extern "C" void kernel_launch(void* const* d_in, const int* in_sizes, int n_in,
                              void* d_out, int out_size)
{
    const float* pred    = (const float*)d_in[0];
    const float* target  = (const float*)d_in[1];
    const float* grid    = (const float*)d_in[2];
    const float* stridem = (const float*)d_in[3];

    int A = in_sizes[3];
    int B = in_sizes[0] / (A * 84);
    int T = in_sizes[1] / (B * 5);
    int BA = B * A;

    k0a_zero<<<1, 32>>>();
    k0b_zero<<<1, 1024>>>();

    dim3 g1((A + 127) / 128, B);
    k1_anchor<<<g1, 128>>>(pred, target, grid, stridem, A, T);

    dim3 g2a(T, B);
    k2a_iou<<<g2a, 128>>>(target, A, T);       // profiler slot 4

    dim3 g2c((T + 7) / 8, B);
    k2c_cost<<<g2c, 256>>>(pred, target, A, T);

    int tot4 = (7 * BA) / 4;
    k4a_fill<<<(tot4 + 255) / 256, 256>>>((float*)d_out, BA);

    k4b_resolve<<<B, 512>>>(pred, target, (float*)d_out, A, T, B);
}

// round 10
// speedup vs baseline: 2.5670x; 1.2250x over previous
#include <cuda_runtime.h>
#include <cuda_fp16.h>
#include <math.h>
#include <float.h>

#define MAXB 16
#define MAXA 33600
#define MAXT 50
#define NCLS 80
#define KC 10
#define LCAP 80
#define LBUF 96
#define BUFCAP 64
#define BUFTOT 80
#define NWI 8                    // warps per k2a block
#define INV_LN2 1.4426950408889634f
#define PEN2 (100000.0f * 1.4426950408889634f)

// Scratch (static __device__ globals)
__device__ int    d_cnt [MAXB];
__device__ int    d_mcnt[MAXB];
__device__ int    d_mlist[MAXB][MAXT * KC + 32];
__device__ int    d_tlen[MAXB * MAXT];
__device__ int    d_tlist[MAXB * MAXT][LCAP];
__device__ float4 d_gbox [MAXB][MAXA];
__device__ uint2  d_gmeta8[MAXB][MAXA];          // half2(xc,yc) | aidx(16b) | half(rad)
__device__ float  d_gS2  [MAXB][MAXA];
__device__ int    d_gaidx[MAXB][MAXA];
__device__ int    d_pos  [MAXB * MAXA];
__device__ int    d_count[MAXB * MAXA];
__device__ int    d_mint [MAXB * MAXA];
__device__ int    d_dk   [MAXB * MAXT];

__global__ void k0a_zero() {
    if (threadIdx.x < MAXB) { d_cnt[threadIdx.x] = 0; d_mcnt[threadIdx.x] = 0; }
}
__global__ void k0b_zero() {
    int i = threadIdx.x;
    if (i < MAXB * MAXT) d_tlen[i] = 0;
}

// ---------- warp-parallel selection helpers ----------
__device__ __forceinline__ void sel_cost(float* bufv, int* bufi, int total,
                                         float* topv, int* topi, int lane)
{
    int rounds = min(KC, total);
    for (int r = 0; r < rounds; r++) {
        float v = FLT_MAX; int id = 0x7fffffff; int sl = 0;
        for (int s = lane; s < total; s += 32) {
            float vv = bufv[s]; int ii = bufi[s];
            if (vv < v || (vv == v && ii < id)) { v = vv; id = ii; sl = s; }
        }
        #pragma unroll
        for (int off = 16; off; off >>= 1) {
            float ov = __shfl_xor_sync(0xffffffffu, v, off);
            int   oi = __shfl_xor_sync(0xffffffffu, id, off);
            int   os = __shfl_xor_sync(0xffffffffu, sl, off);
            if (ov < v || (ov == v && oi < id)) { v = ov; id = oi; sl = os; }
        }
        if (lane == 0) { topv[r] = v; topi[r] = id; bufv[sl] = FLT_MAX; bufi[sl] = 0x7fffffff; }
        __syncwarp();
    }
    if (lane >= rounds && lane < KC) { topv[lane] = FLT_MAX; topi[lane] = 0x7fffffff; }
    __syncwarp();
}

__device__ __forceinline__ void sel_iou(float* bufv, int total, float* topv, int lane)
{
    int rounds = min(KC, total);
    for (int r = 0; r < rounds; r++) {
        float v = -1.f; int sl = 0;
        for (int s = lane; s < total; s += 32) {
            float vv = bufv[s];
            if (vv > v) { v = vv; sl = s; }
        }
        #pragma unroll
        for (int off = 16; off; off >>= 1) {
            float ov = __shfl_xor_sync(0xffffffffu, v, off);
            int   os = __shfl_xor_sync(0xffffffffu, sl, off);
            if (ov > v) { v = ov; sl = os; }
        }
        if (lane == 0) { topv[r] = v; bufv[sl] = -1.f; }
        __syncwarp();
    }
    if (lane >= rounds && lane < KC) topv[lane] = -1.f;
    __syncwarp();
}

// K1: per-anchor. Flags + per-target lists; softplus S2 only for candidate
// warps; compaction (unchanged from R9).
__global__ __launch_bounds__(128) void k1_anchor(
    const float* __restrict__ pred, const float* __restrict__ target,
    const float* __restrict__ grid, const float* __restrict__ stridem,
    int A, int T)
{
    __shared__ float sp[128 * 85];
    __shared__ float st[MAXT * 8];

    int b    = blockIdx.y;
    int base = blockIdx.x * 128;
    int nrows = min(128, A - base);

    const float* predb = pred + ((size_t)b * A + base) * 84;
    for (int i = threadIdx.x; i < nrows * 84; i += 128) {
        int r = i / 84;
        int c = i - r * 84;
        sp[r * 85 + c] = predb[i];
    }
    for (int i = threadIdx.x; i < T; i += 128) {
        const float* tg = target + ((size_t)b * T + i) * 5;
        float x0 = tg[1], y0 = tg[2], x1 = tg[3], y1 = tg[4];
        st[i * 8 + 0] = x0; st[i * 8 + 1] = y0;
        st[i * 8 + 2] = x1; st[i * 8 + 3] = y1;
        st[i * 8 + 4] = 0.5f * (x0 + x1);
        st[i * 8 + 5] = 0.5f * (y0 + y1);
    }
    __syncthreads();

    int tid  = threadIdx.x;
    int lane = tid & 31;
    bool alive = (tid < nrows);
    int a = base + tid;

    bool iba = false;
    float px0 = 0, py0 = 0, px1 = 0, py1 = 0, xc = 0, yc = 0, rad = 0;
    const float* row = sp + tid * 85;

    if (alive) {
        float strv = stridem[a];
        xc  = (grid[2 * a]     + 0.5f) * strv;
        yc  = (grid[2 * a + 1] + 0.5f) * strv;
        rad = 2.5f * strv;
        px0 = row[0]; py0 = row[1]; px1 = row[2]; py1 = row[3];
    }

    bool anyB = false, anyC = false;
    for (int t = 0; t < T; t++) {
        bool inB = false, inC = false;
        if (alive) {
            float tx0 = st[t * 8 + 0], ty0 = st[t * 8 + 1];
            float tx1 = st[t * 8 + 2], ty1 = st[t * 8 + 3];
            float cxt = st[t * 8 + 4], cyt = st[t * 8 + 5];
            inB = fminf(fminf(xc - tx0, yc - ty0), fminf(tx1 - xc, ty1 - yc)) > 0.f;
            inC = fmaxf(fabsf(xc - cxt), fabsf(yc - cyt)) < rad;
            anyB |= inB; anyC |= inC;
        }
        unsigned mb = __ballot_sync(0xffffffffu, inB && inC);
        if (mb) {
            int bt = b * T + t;
            int leader = __ffs(mb) - 1;
            int wb = 0;
            if (lane == leader) wb = atomicAdd(&d_tlen[bt], __popc(mb));
            wb = __shfl_sync(0xffffffffu, wb, leader);
            if (inB && inC) {
                int slot = wb + __popc(mb & ((1u << lane) - 1u));
                if (slot < LCAP) d_tlist[bt][slot] = a;
            }
        }
    }
    iba = alive && (anyB || anyC);

    unsigned m = __ballot_sync(0xffffffffu, iba);
    if (m) {
        float S2 = 0.f;
        if (iba) {
            float P = 1.f;
            int   E = 0;
            #pragma unroll 4
            for (int c = 0; c < NCLS; c++) {
                float e = __expf(row[4 + c]);
                P *= (1.f + e);
                if ((c & 3) == 3) {
                    int bits = __float_as_int(P);
                    E += ((bits >> 23) & 255) - 127;
                    P = __int_as_float((bits & 0x007FFFFF) | 0x3F800000);
                }
            }
            S2 = (float)E + __log2f(P);
        }
        int leader = __ffs(m) - 1;
        int wbase = 0;
        if (lane == leader) wbase = atomicAdd(&d_cnt[b], __popc(m));
        wbase = __shfl_sync(0xffffffffu, wbase, leader);
        if (iba) {
            int pos = wbase + __popc(m & ((1u << lane) - 1u));
            int gi = b * A + a;
            d_pos  [gi] = pos;
            d_count[gi] = 0;
            d_mint [gi] = 0x7fffffff;
            d_gbox [b][pos] = make_float4(px0, py0, px1, py1);
            __half2 hxy = __floats2half2_rn(xc, yc);
            unsigned short hr = __half_as_ushort(__float2half_rn(rad));
            uint2 u;
            u.x = *reinterpret_cast<unsigned*>(&hxy);
            u.y = (unsigned)(a & 0xffff) | ((unsigned)hr << 16);
            d_gmeta8[b][pos] = u;
            d_gS2  [b][pos] = S2;
            d_gaidx[b][pos] = a;
        }
    }
}

// K2a: iou top-10 + dyn_k per (b,t). 8 warps/block, each scans 1/8 of the
// candidates with software prefetch (2 loads in flight) and a division-free
// conservative screen; exact IEEE iou only for pushed (rare) lanes.
__global__ __launch_bounds__(256) void k2a_iou(
    const float* __restrict__ target, int A, int T)
{
    __shared__ float sbiv[NWI][BUFTOT];
    __shared__ float stiv[NWI][KC];
    __shared__ float tpv[KC];

    int t = blockIdx.x, b = blockIdx.y;
    int w = threadIdx.x >> 5, lane = threadIdx.x & 31;
    int N = d_cnt[b];
    int lo = (w * N) >> 3;
    int hi = ((w + 1) * N) >> 3;

    const float* tg = target + ((size_t)b * T + t) * 5;
    float tx0 = tg[1], ty0 = tg[2], tx1 = tg[3], ty1 = tg[4];
    float areaT = (tx1 - tx0) * (ty1 - ty0);

    if (lane < KC) stiv[w][lane] = -1.f;
    __syncwarp();

    float thI = 0.f, qs = 0.f;
    int nb = 0;

    float4 bx = make_float4(0.f, 0.f, 0.f, 0.f);
    if (lo < hi) bx = d_gbox[b][min(lo + lane, hi - 1)];

    for (int base = lo; base < hi; base += 32) {
        // prefetch next iteration's box
        float4 nxt = bx;
        int nbase = base + 32;
        if (nbase < hi) nxt = d_gbox[b][min(nbase + lane, hi - 1)];

        bool valid = (base + lane) < hi;
        float lx = fmaxf(tx0, bx.x), ly = fmaxf(ty0, bx.y);
        float rx = fminf(tx1, bx.z), ry = fminf(ty1, bx.w);
        float ww = fmaxf(rx - lx, 0.f), hh = fmaxf(ry - ly, 0.f);
        float inter = ww * hh;
        float areaP = (bx.z - bx.x) * (bx.w - bx.y);
        float areaS = areaT + areaP;

        bool p = valid && (inter > qs * areaS);
        unsigned mk = __ballot_sync(0xffffffffu, p);
        if (mk) {
            int cnt = __popc(mk);
            if (nb + cnt > BUFCAP) {
                if (lane < KC) sbiv[w][nb + lane] = stiv[w][lane];
                __syncwarp();
                sel_iou(sbiv[w], nb + KC, stiv[w], lane);
                thI = fmaxf(stiv[w][KC - 1], 0.f);
                qs = (thI > 0.f) ? __fdividef(thI, 1.f + thI) * (1.f - 1e-5f) : 0.f;
                nb = 0;
                p = valid && (inter > qs * areaS);
                mk = __ballot_sync(0xffffffffu, p);
                cnt = __popc(mk);
            }
            if (p) {
                float uni = areaS - inter;
                float iou = inter / fmaxf(uni, 1e-9f);   // exact IEEE (rare path)
                sbiv[w][nb + __popc(mk & ((1u << lane) - 1u))] = iou;
            }
            nb += cnt;
        }
        bx = nxt;
    }

    if (lane < KC) sbiv[w][nb + lane] = stiv[w][lane];
    __syncwarp();
    sel_iou(sbiv[w], nb + KC, stiv[w], lane);
    __syncthreads();

    if (w == 0) {
        sel_iou(&stiv[0][0], NWI * KC, tpv, lane);
        if (lane == 0) {
            float s = 0.f;
            #pragma unroll
            for (int r = 0; r < KC; r++) { float v = tpv[r]; if (v > 0.f) s += v; }
            int dk = (int)s;
            d_dk[b * T + t] = max(1, min(KC, dk));
        }
    }
}

// K2c: cost top-10 per (b,t) from the per-target list (<=75 entries,
// all unpenalized -> exact). Rare fallback: full scan with penalty.
__global__ __launch_bounds__(256) void k2c_cost(
    const float* __restrict__ pred, const float* __restrict__ target,
    int A, int T)
{
    __shared__ float bufv[8][LBUF]; __shared__ int bufi[8][LBUF];
    __shared__ float topv[8][KC];   __shared__ int topi[8][KC];

    int w = threadIdx.x >> 5, lane = threadIdx.x & 31;
    int t = blockIdx.x * 8 + w;
    int b = blockIdx.y;
    if (t >= T) return;

    int bt = b * T + t;
    const float* tg = target + ((size_t)b * T + t) * 5;
    int cls = (int)tg[0];
    float tx0 = tg[1], ty0 = tg[2], tx1 = tg[3], ty1 = tg[4];
    float areaT = (tx1 - tx0) * (ty1 - ty0);
    const float* predb = pred + (size_t)b * A * 84;
    int n = d_tlen[bt];

    if (n >= KC) {
        int nn = min(n, LCAP);
        for (int s = lane; s < nn; s += 32) {
            int aidx = d_tlist[bt][s];
            int pos = d_pos[b * A + aidx];
            float4 bx = d_gbox[b][pos];
            float S2 = d_gS2[b][pos];
            float z = predb[(size_t)aidx * 84 + 4 + cls];
            float ct = S2 - z * INV_LN2;
            float lx = fmaxf(tx0, bx.x), ly = fmaxf(ty0, bx.y);
            float rx = fminf(tx1, bx.z), ry = fminf(ty1, bx.w);
            float ww = fmaxf(rx - lx, 0.f), hh = fmaxf(ry - ly, 0.f);
            float inter = ww * hh;
            float areaP = (bx.z - bx.x) * (bx.w - bx.y);
            float uni = areaT + areaP - inter;
            float iou = inter / fmaxf(uni, 1e-9f);
            bufv[w][s] = ct - 3.0f * __log2f(iou + 1e-8f);
            bufi[w][s] = aidx;
        }
        __syncwarp();
        sel_cost(bufv[w], bufi[w], nn, topv[w], topi[w], lane);
    } else {
        int N = d_cnt[b];
        float cxt = 0.5f * (tx0 + tx1), cyt = 0.5f * (ty0 + ty1);
        if (lane < KC) { topv[w][lane] = FLT_MAX; topi[w][lane] = 0x7fffffff; }
        __syncwarp();
        float thv = FLT_MAX; int thi = 0x7fffffff; int nb = 0;

        for (int base = 0; base < N; base += 32) {
            int i = base + lane;
            bool valid = i < N;
            int ii = valid ? i : (N - 1);
            float4 bx = d_gbox[b][ii];
            uint2  mg = d_gmeta8[b][ii];
            float  S2 = d_gS2[b][ii];
            int  aidx = d_gaidx[b][ii];
            float z = predb[(size_t)aidx * 84 + 4 + cls];
            float ct = S2 - z * INV_LN2;
            __half2 hxy = *reinterpret_cast<__half2*>(&mg.x);
            float xc = __low2float(hxy), yc = __high2float(hxy);
            float rad = __half2float(__ushort_as_half((unsigned short)(mg.y >> 16)));

            bool inB = fminf(fminf(xc - tx0, yc - ty0), fminf(tx1 - xc, ty1 - yc)) > 0.f;
            bool inC = fmaxf(fabsf(xc - cxt), fabsf(yc - cyt)) < rad;
            float lx = fmaxf(tx0, bx.x), ly = fmaxf(ty0, bx.y);
            float rx = fminf(tx1, bx.z), ry = fminf(ty1, bx.w);
            float ww = fmaxf(rx - lx, 0.f), hh = fmaxf(ry - ly, 0.f);
            float inter = ww * hh;
            float areaP = (bx.z - bx.x) * (bx.w - bx.y);
            float uni = areaT + areaP - inter;
            float iou = inter / fmaxf(uni, 1e-9f);
            float cost = ct - 3.0f * __log2f(iou + 1e-8f);
            if (!(inB && inC)) cost += PEN2;

            bool pC = valid && (cost < thv || (cost == thv && aidx < thi));
            unsigned mc = __ballot_sync(0xffffffffu, pC);
            if (mc) {
                int cnt = __popc(mc);
                if (nb + cnt > BUFCAP) {
                    if (lane < KC) { bufv[w][nb + lane] = topv[w][lane]; bufi[w][nb + lane] = topi[w][lane]; }
                    __syncwarp();
                    sel_cost(bufv[w], bufi[w], nb + KC, topv[w], topi[w], lane);
                    thv = topv[w][KC - 1]; thi = topi[w][KC - 1];
                    nb = 0;
                    pC = valid && (cost < thv || (cost == thv && aidx < thi));
                    mc = __ballot_sync(0xffffffffu, pC);
                    cnt = __popc(mc);
                }
                if (pC) {
                    int sl = nb + __popc(mc & ((1u << lane) - 1u));
                    bufv[w][sl] = cost; bufi[w][sl] = aidx;
                }
                nb += cnt;
            }
        }
        if (lane < KC) { bufv[w][nb + lane] = topv[w][lane]; bufi[w][nb + lane] = topi[w][lane]; }
        __syncwarp();
        sel_cost(bufv[w], bufi[w], nb + KC, topv[w], topi[w], lane);
    }

    int dk = d_dk[bt];
    if (lane < dk) {
        int id = topi[w][lane];
        if (id != 0x7fffffff) {
            int old = atomicAdd(&d_count[b * A + id], 1);
            atomicMin(&d_mint[b * A + id], t);
            if (old == 0) {
                int p = atomicAdd(&d_mcnt[b], 1);
                d_mlist[b][p] = id;
            }
        }
    }
}

// K4a: streaming default fill (mm=0, box=0, obj=0, cls=80)
__global__ __launch_bounds__(256) void k4a_fill(float* __restrict__ out, int BA)
{
    int n = blockIdx.x * 256 + threadIdx.x;
    int tot = (7 * BA) >> 2;
    if (n < tot) {
        float4 v = (n >= ((6 * BA) >> 2)) ? make_float4(80.f, 80.f, 80.f, 80.f)
                                          : make_float4(0.f, 0.f, 0.f, 0.f);
        ((float4*)out)[n] = v;
    }
}

// K4b: resolve only matched anchors (from per-image match list)
__global__ __launch_bounds__(512) void k4b_resolve(
    const float* __restrict__ pred, const float* __restrict__ target,
    float* __restrict__ out, int A, int T, int B)
{
    __shared__ float st[MAXT * 5];
    int b = blockIdx.x;
    for (int j = threadIdx.x; j < T * 5; j += 512)
        st[j] = target[(size_t)b * T * 5 + j];
    __syncthreads();

    int m = d_mcnt[b];
    int BA = B * A;
    const float* predb = pred + (size_t)b * A * 84;
    for (int j = threadIdx.x; j < m; j += 512) {
        int id  = d_mlist[b][j];
        int gi  = b * A + id;
        int c   = d_count[gi];
        int pos = d_pos[gi];
        float4 bx = d_gbox[b][pos];
        uint2  mg = d_gmeta8[b][pos];
        float  S2 = d_gS2[b][pos];
        __half2 hxy = *reinterpret_cast<__half2*>(&mg.x);
        float xc = __low2float(hxy), yc = __high2float(hxy);
        float rad = __half2float(__ushort_as_half((unsigned short)(mg.y >> 16)));
        float areaP = (bx.z - bx.x) * (bx.w - bx.y);

        float maxiou = 0.f, bestC = FLT_MAX;
        int bestT = 0;
        bool conflict = (c > 1);

        for (int t = 0; t < T; t++) {
            float tx0 = st[t * 5 + 1], ty0 = st[t * 5 + 2];
            float tx1 = st[t * 5 + 3], ty1 = st[t * 5 + 4];
            float lx = fmaxf(tx0, bx.x), ly = fmaxf(ty0, bx.y);
            float rx = fminf(tx1, bx.z), ry = fminf(ty1, bx.w);
            float w2 = fmaxf(rx - lx, 0.f), h2 = fmaxf(ry - ly, 0.f);
            float inter = w2 * h2;
            float areaT = (tx1 - tx0) * (ty1 - ty0);
            float uni = areaT + areaP - inter;
            float iou = inter / fmaxf(uni, 1e-9f);
            maxiou = fmaxf(maxiou, iou);
            if (conflict) {
                int cls = (int)st[t * 5 + 0];
                float z = predb[(size_t)id * 84 + 4 + cls];
                float ct = S2 - z * INV_LN2;
                float cx = 0.5f * (tx0 + tx1), cy = 0.5f * (ty0 + ty1);
                bool inB = fminf(fminf(xc - tx0, yc - ty0), fminf(tx1 - xc, ty1 - yc)) > 0.f;
                bool inC = fmaxf(fabsf(xc - cx), fabsf(yc - cy)) < rad;
                float cost = ct - 3.0f * __log2f(iou + 1e-8f);
                if (!(inB && inC)) cost += PEN2;
                if (cost < bestC) { bestC = cost; bestT = t; }
            }
        }

        int tt = conflict ? bestT : d_mint[gi];
        out[gi] = 1.f;
        ((float4*)(out + BA))[gi] = make_float4(st[tt * 5 + 1], st[tt * 5 + 2],
                                                st[tt * 5 + 3], st[tt * 5 + 4]);
        out[(size_t)5 * BA + gi] = maxiou;
        out[(size_t)6 * BA + gi] = st[tt * 5 + 0];
    }
}

extern "C" void kernel_launch(void* const* d_in, const int* in_sizes, int n_in,
                              void* d_out, int out_size)
{
    const float* pred    = (const float*)d_in[0];
    const float* target  = (const float*)d_in[1];
    const float* grid    = (const float*)d_in[2];
    const float* stridem = (const float*)d_in[3];

    int A = in_sizes[3];
    int B = in_sizes[0] / (A * 84);
    int T = in_sizes[1] / (B * 5);
    int BA = B * A;

    k0a_zero<<<1, 32>>>();
    k0b_zero<<<1, 1024>>>();

    dim3 g1((A + 127) / 128, B);
    k1_anchor<<<g1, 128>>>(pred, target, grid, stridem, A, T);

    dim3 g2a(T, B);
    k2a_iou<<<g2a, 256>>>(target, A, T);       // profiler slot 4

    dim3 g2c((T + 7) / 8, B);
    k2c_cost<<<g2c, 256>>>(pred, target, A, T);

    int tot4 = (7 * BA) / 4;
    k4a_fill<<<(tot4 + 255) / 256, 256>>>((float*)d_out, BA);

    k4b_resolve<<<B, 512>>>(pred, target, (float*)d_out, A, T, B);
}